// round 1
// baseline (speedup 1.0000x reference)
#include <cuda_runtime.h>
#include <cuda_bf16.h>
#include <math_constants.h>

// Problem constants
#define BB 2
#define LL 2048
#define HD 1024
#define NH 16
#define DH 64
#define ML (BB*LL)          // 4096 total rows

// ---------------- scratch (device globals; no runtime allocation) ----------------
__device__ float g_q[ML * HD];         // 16 MB
__device__ float g_kv[ML * 2 * HD];    // 32 MB
__device__ float g_attn[ML * HD];      // 16 MB

// ---------------- fused-bias SGEMM: C[M,N] = A[M,K] @ B[K,N] + bias[N] ----------------
#define BM 128
#define BN 128
#define BK 16
#define TM 8
#define TN 8

__global__ __launch_bounds__(256, 2)
void sgemm_bias_kernel(const float* __restrict__ A, const float* __restrict__ B,
                       const float* __restrict__ bias, float* __restrict__ C,
                       int M, int N, int K) {
    __shared__ float As[BK][BM + 4];   // transposed, padded
    __shared__ float Bs[BK][BN];

    const int tid  = threadIdx.x;                 // 256 threads
    const int brow = blockIdx.y * BM;
    const int bcol = blockIdx.x * BN;
    const int tr   = (tid / 16) * TM;
    const int tc   = (tid % 16) * TN;

    // load indexing
    const int aRow = tid / 4;            // 0..63 (x2 -> 128 rows)
    const int aK4  = (tid % 4) * 4;      // k offset (float4)
    const int bRow = tid / 32;           // 0..7  (x2 -> 16 rows)
    const int bCol = (tid % 32) * 4;

    float acc[TM][TN];
    #pragma unroll
    for (int i = 0; i < TM; ++i)
        #pragma unroll
        for (int j = 0; j < TN; ++j) acc[i][j] = 0.0f;

    for (int k0 = 0; k0 < K; k0 += BK) {
        #pragma unroll
        for (int i = 0; i < 2; ++i) {
            int m = aRow + i * 64;
            float4 av = *reinterpret_cast<const float4*>(&A[(size_t)(brow + m) * K + k0 + aK4]);
            As[aK4 + 0][m] = av.x;
            As[aK4 + 1][m] = av.y;
            As[aK4 + 2][m] = av.z;
            As[aK4 + 3][m] = av.w;
        }
        #pragma unroll
        for (int i = 0; i < 2; ++i) {
            int kk = bRow + i * 8;
            *reinterpret_cast<float4*>(&Bs[kk][bCol]) =
                *reinterpret_cast<const float4*>(&B[(size_t)(k0 + kk) * N + bcol + bCol]);
        }
        __syncthreads();

        #pragma unroll
        for (int kk = 0; kk < BK; ++kk) {
            float rm[TM], rn[TN];
            #pragma unroll
            for (int i = 0; i < TM; ++i) rm[i] = As[kk][tr + i];
            #pragma unroll
            for (int j = 0; j < TN; ++j) rn[j] = Bs[kk][tc + j];
            #pragma unroll
            for (int i = 0; i < TM; ++i)
                #pragma unroll
                for (int j = 0; j < TN; ++j)
                    acc[i][j] = fmaf(rm[i], rn[j], acc[i][j]);
        }
        __syncthreads();
    }

    // epilogue: + bias, vectorized stores
    #pragma unroll
    for (int i = 0; i < TM; ++i) {
        size_t base = (size_t)(brow + tr + i) * N + bcol + tc;
        #pragma unroll
        for (int v = 0; v < TN / 4; ++v) {
            float4 o;
            o.x = acc[i][v*4+0] + bias[bcol + tc + v*4 + 0];
            o.y = acc[i][v*4+1] + bias[bcol + tc + v*4 + 1];
            o.z = acc[i][v*4+2] + bias[bcol + tc + v*4 + 2];
            o.w = acc[i][v*4+3] + bias[bcol + tc + v*4 + 3];
            *reinterpret_cast<float4*>(&C[base + v*4]) = o;
        }
    }
}

// ---------------- flash attention (causal + key-padding mask), fp32 ----------------
// One block per (q-tile of 64 rows, head, batch). 256 threads = 8 warps, 8 q-rows/warp.
// Online softmax; K stored d-major (padded) for conflict-free LDS; P tile is warp-private.

#define SM_QS   0                       // 64*64
#define SM_KT   (64*64)                 // 64*65 (padded stride 65)
#define SM_VS   (SM_KT + 64*65)         // 64*64
#define SM_PS   (SM_VS + 64*64)         // 64*64
#define SM_MA   (SM_PS + 64*64)         // 64
#define ATT_SMEM_FLOATS (SM_MA + 64)

__global__ __launch_bounds__(256)
void attn_kernel(const float* __restrict__ q, const float* __restrict__ kv,
                 const unsigned char* __restrict__ mask, float* __restrict__ o) {
    extern __shared__ float sm[];
    float* Qs = sm + SM_QS;
    float* Kt = sm + SM_KT;
    float* Vs = sm + SM_VS;
    float* Ps = sm + SM_PS;
    float* Ma = sm + SM_MA;

    const int qt = blockIdx.x;          // 0..31
    const int h  = blockIdx.y;          // 0..15
    const int b  = blockIdx.z;          // 0..1
    const int tid  = threadIdx.x;
    const int warp = tid >> 5;
    const int lane = tid & 31;
    const int wrow = warp * 8;          // first q-row of this warp (within tile)
    const int c0 = lane, c1 = lane + 32;
    const float scale = 0.125f;         // 1/sqrt(64)

    // load Q tile (pre-scaled)
    for (int idx = tid; idx < 64 * 64; idx += 256) {
        int r = idx >> 6, d = idx & 63;
        Qs[idx] = q[(size_t)(b * LL + qt * 64 + r) * HD + h * DH + d] * scale;
    }

    float Oa[8], Ob[8], mrow[8], lrow[8];
    #pragma unroll
    for (int rr = 0; rr < 8; ++rr) { Oa[rr] = 0.f; Ob[rr] = 0.f; mrow[rr] = -CUDART_INF_F; lrow[rr] = 0.f; }

    for (int kt = 0; kt <= qt; ++kt) {
        // load K (d-major, padded) and V tiles
        for (int idx = tid; idx < 64 * 64; idx += 256) {
            int kk = idx >> 6, d = idx & 63;
            size_t base = (size_t)(b * LL + kt * 64 + kk) * (2 * HD) + h * DH + d;
            Kt[d * 65 + kk] = kv[base];
            Vs[kk * 64 + d] = kv[base + HD];
        }
        if (tid < 64) Ma[tid] = mask[b * LL + kt * 64 + tid] ? -1e30f : 0.0f;
        __syncthreads();

        // S = Q K^T  (each lane: 8 rows x 2 key-cols)
        float a0[8], a1[8];
        #pragma unroll
        for (int rr = 0; rr < 8; ++rr) { a0[rr] = 0.f; a1[rr] = 0.f; }
        #pragma unroll 4
        for (int d = 0; d < 64; ++d) {
            float k0 = Kt[d * 65 + c0];
            float k1 = Kt[d * 65 + c1];
            #pragma unroll
            for (int rr = 0; rr < 8; ++rr) {
                float qv = Qs[(wrow + rr) * 64 + d];
                a0[rr] = fmaf(qv, k0, a0[rr]);
                a1[rr] = fmaf(qv, k1, a1[rr]);
            }
        }

        // masks + online softmax per row
        const float ma0 = Ma[c0], ma1 = Ma[c1];
        const bool diag = (kt == qt);
        #pragma unroll
        for (int rr = 0; rr < 8; ++rr) {
            int r = wrow + rr;
            float s0 = a0[rr] + ma0;
            float s1 = a1[rr] + ma1;
            if (diag) {
                if (c0 > r) s0 = -1e30f;
                if (c1 > r) s1 = -1e30f;
            }
            float mx = fmaxf(s0, s1);
            #pragma unroll
            for (int off = 16; off > 0; off >>= 1)
                mx = fmaxf(mx, __shfl_xor_sync(0xffffffffu, mx, off));
            float mnew = fmaxf(mrow[rr], mx);
            float p0 = __expf(s0 - mnew);
            float p1 = __expf(s1 - mnew);
            float ps = p0 + p1;
            #pragma unroll
            for (int off = 16; off > 0; off >>= 1)
                ps += __shfl_xor_sync(0xffffffffu, ps, off);
            float alpha = __expf(mrow[rr] - mnew);   // 0 on first tile (m=-inf)
            lrow[rr] = lrow[rr] * alpha + ps;
            mrow[rr] = mnew;
            Oa[rr] *= alpha;
            Ob[rr] *= alpha;
            Ps[r * 64 + c0] = p0;
            Ps[r * 64 + c1] = p1;
        }
        __syncwarp();   // P rows are warp-private; warp-level visibility suffices

        // O += P V  (each lane: 8 rows x 2 d-cols)
        #pragma unroll 4
        for (int k = 0; k < 64; ++k) {
            float v0 = Vs[k * 64 + c0];
            float v1 = Vs[k * 64 + c1];
            #pragma unroll
            for (int rr = 0; rr < 8; ++rr) {
                float pv = Ps[(wrow + rr) * 64 + k];
                Oa[rr] = fmaf(pv, v0, Oa[rr]);
                Ob[rr] = fmaf(pv, v1, Ob[rr]);
            }
        }
        __syncthreads();   // before K/V tiles are overwritten
    }

    // epilogue: normalize and store (b, l, h*64+d) layout
    #pragma unroll
    for (int rr = 0; rr < 8; ++rr) {
        float inv = 1.0f / lrow[rr];
        size_t base = (size_t)(b * LL + qt * 64 + wrow + rr) * HD + h * DH;
        o[base + c0] = Oa[rr] * inv;
        o[base + c1] = Ob[rr] * inv;
    }
}

// ---------------- launch ----------------
extern "C" void kernel_launch(void* const* d_in, const int* in_sizes, int n_in,
                              void* d_out, int out_size) {
    const float*         x      = (const float*)d_in[0];
    const float*         y      = (const float*)d_in[1];
    const unsigned char* mask   = (const unsigned char*)d_in[2];
    const float*         Wq_w   = (const float*)d_in[3];
    const float*         Wq_b   = (const float*)d_in[4];
    const float*         Wkv_w  = (const float*)d_in[5];
    const float*         Wkv_b  = (const float*)d_in[6];
    const float*         proj_w = (const float*)d_in[7];
    const float*         proj_b = (const float*)d_in[8];
    float*               out    = (float*)d_out;

    void *pq = nullptr, *pkv = nullptr, *pattn = nullptr;
    cudaGetSymbolAddress(&pq, g_q);
    cudaGetSymbolAddress(&pkv, g_kv);
    cudaGetSymbolAddress(&pattn, g_attn);
    float* q_buf    = (float*)pq;
    float* kv_buf   = (float*)pkv;
    float* attn_buf = (float*)pattn;

    const int att_smem = ATT_SMEM_FLOATS * sizeof(float);   // ~66 KB > 48 KB default
    cudaFuncSetAttribute(attn_kernel, cudaFuncAttributeMaxDynamicSharedMemorySize, att_smem);

    // q = x @ Wq + b            (4096 x 1024 x 1024)
    sgemm_bias_kernel<<<dim3(HD / BN, ML / BM), 256>>>(x, Wq_w, Wq_b, q_buf, ML, HD, HD);
    // kv = y @ Wkv + b          (4096 x 2048 x 1024)
    sgemm_bias_kernel<<<dim3(2 * HD / BN, ML / BM), 256>>>(y, Wkv_w, Wkv_b, kv_buf, ML, 2 * HD, HD);
    // attention
    attn_kernel<<<dim3(LL / 64, NH, BB), 256, att_smem>>>(q_buf, kv_buf, mask, attn_buf);
    // out = attn @ proj + b     (4096 x 1024 x 1024)
    sgemm_bias_kernel<<<dim3(HD / BN, ML / BM), 256>>>(attn_buf, proj_w, proj_b, out, ML, HD, HD);
}

// round 4
// speedup vs baseline: 1.7415x; 1.7415x over previous
#include <cuda_runtime.h>
#include <cuda_bf16.h>
#include <math_constants.h>
#include <cstdint>

// Problem constants
#define BB 2
#define LL 2048
#define HD 1024
#define NH 16
#define DH 64
#define ML (BB*LL)          // 4096 total rows

// ---------------- scratch (device globals; no runtime allocation) ----------------
__device__ float g_q[ML * HD];         // 16 MB
__device__ float g_kv[ML * 2 * HD];    // 32 MB
__device__ float g_attn[ML * HD];      // 16 MB

// ---------------- tf32 helpers ----------------
__device__ __forceinline__ float tf32r(float x) {
    uint32_t u;
    asm("cvt.rna.tf32.f32 %0, %1;" : "=r"(u) : "f"(x));
    return __uint_as_float(u);
}

__device__ __forceinline__ void mma_tf32(float c[4], const uint32_t a[4], const uint32_t b[2]) {
    asm volatile(
        "mma.sync.aligned.m16n8k8.row.col.f32.tf32.tf32.f32 "
        "{%0,%1,%2,%3}, {%4,%5,%6,%7}, {%8,%9}, {%0,%1,%2,%3};"
        : "+f"(c[0]), "+f"(c[1]), "+f"(c[2]), "+f"(c[3])
        : "r"(a[0]), "r"(a[1]), "r"(a[2]), "r"(a[3]),
          "r"(b[0]), "r"(b[1]));
}

// ---------------- tf32 tensor-core GEMM: C[M,N] = A[M,K] @ B[K,N] + bias[N] ----------------
// Block 128x128, BK=32, 256 threads = 8 warps (4x2), warp tile 32x64.
#define GBM 128
#define GBN 128
#define GBK 32
#define ASTR 36     // A smem row stride (conflict-free frag reads)
#define BSTR 136    // B smem row stride

__global__ __launch_bounds__(256, 2)
void tf32gemm_bias(const float* __restrict__ A, const float* __restrict__ B,
                   const float* __restrict__ bias, float* __restrict__ C,
                   int M, int N, int K) {
    __shared__ float As[GBM][ASTR];   // 18432 B
    __shared__ float Bs[GBK][BSTR];   // 17408 B

    const int tid  = threadIdx.x;
    const int lane = tid & 31;
    const int warp = tid >> 5;
    const int g = lane >> 2, t = lane & 3;
    const int wm = warp & 3;          // 0..3
    const int wn = warp >> 2;         // 0..1
    const int brow = blockIdx.y * GBM;
    const int bcol = blockIdx.x * GBN;

    // load indexing
    const int ar = tid >> 3;              // 0..31 (+i*32)
    const int ac = (tid & 7) * 4;         // 0..28
    const int brl = tid >> 5;             // 0..7 (+i*8)
    const int bcl = (tid & 31) * 4;       // 0..124

    float acc[2][8][4];
    #pragma unroll
    for (int mf = 0; mf < 2; ++mf)
        #pragma unroll
        for (int nf = 0; nf < 8; ++nf)
            #pragma unroll
            for (int r = 0; r < 4; ++r) acc[mf][nf][r] = 0.0f;

    for (int k0 = 0; k0 < K; k0 += GBK) {
        // A tile 128x32 (converted to tf32 at store)
        #pragma unroll
        for (int i = 0; i < 4; ++i) {
            int r = ar + i * 32;
            float4 v = *reinterpret_cast<const float4*>(&A[(size_t)(brow + r) * K + k0 + ac]);
            float4 w = make_float4(tf32r(v.x), tf32r(v.y), tf32r(v.z), tf32r(v.w));
            *reinterpret_cast<float4*>(&As[r][ac]) = w;
        }
        // B tile 32x128
        #pragma unroll
        for (int i = 0; i < 4; ++i) {
            int r = brl + i * 8;
            float4 v = *reinterpret_cast<const float4*>(&B[(size_t)(k0 + r) * N + bcol + bcl]);
            float4 w = make_float4(tf32r(v.x), tf32r(v.y), tf32r(v.z), tf32r(v.w));
            *reinterpret_cast<float4*>(&Bs[r][bcl]) = w;
        }
        __syncthreads();

        #pragma unroll
        for (int kk = 0; kk < 4; ++kk) {
            const int k = kk * 8;
            uint32_t af[2][4], bf[8][2];
            #pragma unroll
            for (int mf = 0; mf < 2; ++mf) {
                int rb = wm * 32 + mf * 16;
                af[mf][0] = __float_as_uint(As[rb + g][k + t]);
                af[mf][1] = __float_as_uint(As[rb + g + 8][k + t]);
                af[mf][2] = __float_as_uint(As[rb + g][k + t + 4]);
                af[mf][3] = __float_as_uint(As[rb + g + 8][k + t + 4]);
            }
            #pragma unroll
            for (int nf = 0; nf < 8; ++nf) {
                int cb = wn * 64 + nf * 8 + g;
                bf[nf][0] = __float_as_uint(Bs[k + t][cb]);
                bf[nf][1] = __float_as_uint(Bs[k + t + 4][cb]);
            }
            #pragma unroll
            for (int mf = 0; mf < 2; ++mf)
                #pragma unroll
                for (int nf = 0; nf < 8; ++nf)
                    mma_tf32(acc[mf][nf], af[mf], bf[nf]);
        }
        __syncthreads();
    }

    // epilogue: + bias, float2 stores (c0/c1 and c2/c3 are adjacent columns)
    #pragma unroll
    for (int mf = 0; mf < 2; ++mf) {
        #pragma unroll
        for (int nf = 0; nf < 8; ++nf) {
            int col  = bcol + wn * 64 + nf * 8 + 2 * t;
            int row0 = brow + wm * 32 + mf * 16 + g;
            float2 bi = *reinterpret_cast<const float2*>(&bias[col]);
            float2 o0 = make_float2(acc[mf][nf][0] + bi.x, acc[mf][nf][1] + bi.y);
            float2 o1 = make_float2(acc[mf][nf][2] + bi.x, acc[mf][nf][3] + bi.y);
            *reinterpret_cast<float2*>(&C[(size_t)row0 * N + col]) = o0;
            *reinterpret_cast<float2*>(&C[(size_t)(row0 + 8) * N + col]) = o1;
        }
    }
}

// ---------------- flash attention (causal + key-padding mask), fp32 ----------------
// One block per (64-row q-tile, head, batch). 8 warps, 8 q-rows/warp.
// Lane owns key/output columns c0=2*lane, c1=2*lane+1.
// K,V smem rows stride 66 (float2 reads conflict-free); Q,P rows broadcast float4.

#define KVSTR 66
#define SM_QS   0                           // 64*64
#define SM_KT   (64*64)                     // 64*66  (d-major: Kt[d][key])
#define SM_VS   (SM_KT + 64*KVSTR)          // 64*66  (k-major: Vs[key][d])
#define SM_PS   (SM_VS + 64*KVSTR)          // 64*64
#define SM_MA   (SM_PS + 64*64)             // 64
#define ATT_SMEM_FLOATS (SM_MA + 64)

__global__ __launch_bounds__(256)
void attn_kernel(const float* __restrict__ q, const float* __restrict__ kv,
                 const unsigned char* __restrict__ mask, float* __restrict__ o) {
    extern __shared__ float sm[];
    float* Qs = sm + SM_QS;
    float* Kt = sm + SM_KT;
    float* Vs = sm + SM_VS;
    float* Ps = sm + SM_PS;
    float* Ma = sm + SM_MA;

    const int qt = blockIdx.x;
    const int h  = blockIdx.y;
    const int b  = blockIdx.z;
    const int tid  = threadIdx.x;
    const int warp = tid >> 5;
    const int lane = tid & 31;
    const int wrow = warp * 8;
    const int c0 = 2 * lane, c1 = 2 * lane + 1;
    const float scale = 0.125f;

    // load Q tile (pre-scaled), row-major stride 64
    for (int idx = tid; idx < 64 * 64; idx += 256) {
        int r = idx >> 6, d = idx & 63;
        Qs[idx] = q[(size_t)(b * LL + qt * 64 + r) * HD + h * DH + d] * scale;
    }

    float Oa[8], Ob[8], mrow[8], lrow[8];
    #pragma unroll
    for (int rr = 0; rr < 8; ++rr) { Oa[rr] = 0.f; Ob[rr] = 0.f; mrow[rr] = -CUDART_INF_F; lrow[rr] = 0.f; }

    const float2* Kt2 = reinterpret_cast<const float2*>(Kt);  // row stride 33 float2
    const float2* Vs2 = reinterpret_cast<const float2*>(Vs);

    for (int kt = 0; kt <= qt; ++kt) {
        // load K (d-major) and V (k-major) tiles; coalesced global reads
        for (int idx = tid; idx < 64 * 64; idx += 256) {
            int kk = idx >> 6, d = idx & 63;
            size_t base = (size_t)(b * LL + kt * 64 + kk) * (2 * HD) + h * DH + d;
            Kt[d * KVSTR + kk] = kv[base];
            Vs[kk * KVSTR + d] = kv[base + HD];
        }
        if (tid < 64) Ma[tid] = mask[b * LL + kt * 64 + tid] ? -1e30f : 0.0f;
        __syncthreads();

        // ---- S = Q K^T : lane computes 8 rows x 2 key-cols ----
        float a0[8], a1[8];
        #pragma unroll
        for (int rr = 0; rr < 8; ++rr) { a0[rr] = 0.f; a1[rr] = 0.f; }
        #pragma unroll
        for (int d4 = 0; d4 < 64; d4 += 4) {
            float2 k0v = Kt2[(d4 + 0) * 33 + lane];
            float2 k1v = Kt2[(d4 + 1) * 33 + lane];
            float2 k2v = Kt2[(d4 + 2) * 33 + lane];
            float2 k3v = Kt2[(d4 + 3) * 33 + lane];
            #pragma unroll
            for (int rr = 0; rr < 8; ++rr) {
                float4 qv = *reinterpret_cast<const float4*>(&Qs[(wrow + rr) * 64 + d4]);
                a0[rr] = fmaf(qv.x, k0v.x, a0[rr]); a1[rr] = fmaf(qv.x, k0v.y, a1[rr]);
                a0[rr] = fmaf(qv.y, k1v.x, a0[rr]); a1[rr] = fmaf(qv.y, k1v.y, a1[rr]);
                a0[rr] = fmaf(qv.z, k2v.x, a0[rr]); a1[rr] = fmaf(qv.z, k2v.y, a1[rr]);
                a0[rr] = fmaf(qv.w, k3v.x, a0[rr]); a1[rr] = fmaf(qv.w, k3v.y, a1[rr]);
            }
        }

        // ---- masks + online softmax per row ----
        const float ma0 = Ma[c0], ma1 = Ma[c1];
        const bool diag = (kt == qt);
        #pragma unroll
        for (int rr = 0; rr < 8; ++rr) {
            int r = wrow + rr;
            float s0 = a0[rr] + ma0;
            float s1 = a1[rr] + ma1;
            if (diag) {
                if (c0 > r) s0 = -1e30f;
                if (c1 > r) s1 = -1e30f;
            }
            float mx = fmaxf(s0, s1);
            #pragma unroll
            for (int off = 16; off > 0; off >>= 1)
                mx = fmaxf(mx, __shfl_xor_sync(0xffffffffu, mx, off));
            float mnew = fmaxf(mrow[rr], mx);
            float p0 = __expf(s0 - mnew);
            float p1 = __expf(s1 - mnew);
            float ps = p0 + p1;
            #pragma unroll
            for (int off = 16; off > 0; off >>= 1)
                ps += __shfl_xor_sync(0xffffffffu, ps, off);
            float alpha = __expf(mrow[rr] - mnew);
            lrow[rr] = lrow[rr] * alpha + ps;
            mrow[rr] = mnew;
            Oa[rr] *= alpha;
            Ob[rr] *= alpha;
            *reinterpret_cast<float2*>(&Ps[r * 64 + c0]) = make_float2(p0, p1);
        }
        __syncwarp();   // P rows are warp-private

        // ---- O += P V : lane computes 8 rows x 2 d-cols ----
        #pragma unroll
        for (int k4 = 0; k4 < 64; k4 += 4) {
            float2 v0 = Vs2[(k4 + 0) * 33 + lane];
            float2 v1 = Vs2[(k4 + 1) * 33 + lane];
            float2 v2 = Vs2[(k4 + 2) * 33 + lane];
            float2 v3 = Vs2[(k4 + 3) * 33 + lane];
            #pragma unroll
            for (int rr = 0; rr < 8; ++rr) {
                float4 pv = *reinterpret_cast<const float4*>(&Ps[(wrow + rr) * 64 + k4]);
                Oa[rr] = fmaf(pv.x, v0.x, Oa[rr]); Ob[rr] = fmaf(pv.x, v0.y, Ob[rr]);
                Oa[rr] = fmaf(pv.y, v1.x, Oa[rr]); Ob[rr] = fmaf(pv.y, v1.y, Ob[rr]);
                Oa[rr] = fmaf(pv.z, v2.x, Oa[rr]); Ob[rr] = fmaf(pv.z, v2.y, Ob[rr]);
                Oa[rr] = fmaf(pv.w, v3.x, Oa[rr]); Ob[rr] = fmaf(pv.w, v3.y, Ob[rr]);
            }
        }
        __syncthreads();   // before K/V tiles are overwritten
    }

    // epilogue: normalize, float2 store
    #pragma unroll
    for (int rr = 0; rr < 8; ++rr) {
        float inv = 1.0f / lrow[rr];
        size_t base = (size_t)(b * LL + qt * 64 + wrow + rr) * HD + h * DH;
        *reinterpret_cast<float2*>(&o[base + c0]) = make_float2(Oa[rr] * inv, Ob[rr] * inv);
    }
}

// ---------------- launch ----------------
extern "C" void kernel_launch(void* const* d_in, const int* in_sizes, int n_in,
                              void* d_out, int out_size) {
    const float*         x      = (const float*)d_in[0];
    const float*         y      = (const float*)d_in[1];
    const unsigned char* mask   = (const unsigned char*)d_in[2];
    const float*         Wq_w   = (const float*)d_in[3];
    const float*         Wq_b   = (const float*)d_in[4];
    const float*         Wkv_w  = (const float*)d_in[5];
    const float*         Wkv_b  = (const float*)d_in[6];
    const float*         proj_w = (const float*)d_in[7];
    const float*         proj_b = (const float*)d_in[8];
    float*               out    = (float*)d_out;

    void *pq = nullptr, *pkv = nullptr, *pattn = nullptr;
    cudaGetSymbolAddress(&pq, g_q);
    cudaGetSymbolAddress(&pkv, g_kv);
    cudaGetSymbolAddress(&pattn, g_attn);
    float* q_buf    = (float*)pq;
    float* kv_buf   = (float*)pkv;
    float* attn_buf = (float*)pattn;

    const int att_smem = ATT_SMEM_FLOATS * sizeof(float);
    cudaFuncSetAttribute(attn_kernel, cudaFuncAttributeMaxDynamicSharedMemorySize, att_smem);

    // q = x @ Wq + b            (4096 x 1024 x 1024)
    tf32gemm_bias<<<dim3(HD / GBN, ML / GBM), 256>>>(x, Wq_w, Wq_b, q_buf, ML, HD, HD);
    // kv = y @ Wkv + b          (4096 x 2048 x 1024)
    tf32gemm_bias<<<dim3(2 * HD / GBN, ML / GBM), 256>>>(y, Wkv_w, Wkv_b, kv_buf, ML, 2 * HD, HD);
    // attention
    attn_kernel<<<dim3(LL / 64, NH, BB), 256, att_smem>>>(q_buf, kv_buf, mask, attn_buf);
    // out = attn @ proj + b     (4096 x 1024 x 1024)
    tf32gemm_bias<<<dim3(HD / GBN, ML / GBM), 256>>>(attn_buf, proj_w, proj_b, out, ML, HD, HD);
}

// round 6
// speedup vs baseline: 2.2622x; 1.2990x over previous
#include <cuda_runtime.h>
#include <cuda_bf16.h>
#include <math_constants.h>
#include <cstdint>

// Problem constants
#define BB 2
#define LL 2048
#define HD 1024
#define NH 16
#define DH 64
#define ML (BB*LL)          // 4096 total rows

// ---------------- scratch (device globals; no runtime allocation) ----------------
__device__ float g_q[ML * HD];         // 16 MB
__device__ float g_kv[ML * 2 * HD];    // 32 MB
__device__ float g_attn[ML * HD];      // 16 MB

// ---------------- tf32 helpers ----------------
__device__ __forceinline__ float tf32r(float x) {
    uint32_t u;
    asm("cvt.rna.tf32.f32 %0, %1;" : "=r"(u) : "f"(x));
    return __uint_as_float(u);
}

__device__ __forceinline__ void mma_tf32(float c[4], const uint32_t a[4], const uint32_t b[2]) {
    asm volatile(
        "mma.sync.aligned.m16n8k8.row.col.f32.tf32.tf32.f32 "
        "{%0,%1,%2,%3}, {%4,%5,%6,%7}, {%8,%9}, {%0,%1,%2,%3};"
        : "+f"(c[0]), "+f"(c[1]), "+f"(c[2]), "+f"(c[3])
        : "r"(a[0]), "r"(a[1]), "r"(a[2]), "r"(a[3]),
          "r"(b[0]), "r"(b[1]));
}

// ---------------- tf32 tensor-core GEMM: C[M,N] = A[M,K] @ B[K,N] + bias[N] ----------------
#define GBM 128
#define GBN 128
#define GBK 32
#define ASTR 36
#define BSTR 136

__global__ __launch_bounds__(256, 2)
void tf32gemm_bias(const float* __restrict__ A, const float* __restrict__ B,
                   const float* __restrict__ bias, float* __restrict__ C,
                   int M, int N, int K) {
    __shared__ float As[GBM][ASTR];
    __shared__ float Bs[GBK][BSTR];

    const int tid  = threadIdx.x;
    const int lane = tid & 31;
    const int warp = tid >> 5;
    const int g = lane >> 2, t = lane & 3;
    const int wm = warp & 3;
    const int wn = warp >> 2;
    const int brow = blockIdx.y * GBM;
    const int bcol = blockIdx.x * GBN;

    const int ar = tid >> 3;
    const int ac = (tid & 7) * 4;
    const int brl = tid >> 5;
    const int bcl = (tid & 31) * 4;

    float acc[2][8][4];
    #pragma unroll
    for (int mf = 0; mf < 2; ++mf)
        #pragma unroll
        for (int nf = 0; nf < 8; ++nf)
            #pragma unroll
            for (int r = 0; r < 4; ++r) acc[mf][nf][r] = 0.0f;

    for (int k0 = 0; k0 < K; k0 += GBK) {
        #pragma unroll
        for (int i = 0; i < 4; ++i) {
            int r = ar + i * 32;
            float4 v = *reinterpret_cast<const float4*>(&A[(size_t)(brow + r) * K + k0 + ac]);
            float4 w = make_float4(tf32r(v.x), tf32r(v.y), tf32r(v.z), tf32r(v.w));
            *reinterpret_cast<float4*>(&As[r][ac]) = w;
        }
        #pragma unroll
        for (int i = 0; i < 4; ++i) {
            int r = brl + i * 8;
            float4 v = *reinterpret_cast<const float4*>(&B[(size_t)(k0 + r) * N + bcol + bcl]);
            float4 w = make_float4(tf32r(v.x), tf32r(v.y), tf32r(v.z), tf32r(v.w));
            *reinterpret_cast<float4*>(&Bs[r][bcl]) = w;
        }
        __syncthreads();

        #pragma unroll
        for (int kk = 0; kk < 4; ++kk) {
            const int k = kk * 8;
            uint32_t af[2][4], bf[8][2];
            #pragma unroll
            for (int mf = 0; mf < 2; ++mf) {
                int rb = wm * 32 + mf * 16;
                af[mf][0] = __float_as_uint(As[rb + g][k + t]);
                af[mf][1] = __float_as_uint(As[rb + g + 8][k + t]);
                af[mf][2] = __float_as_uint(As[rb + g][k + t + 4]);
                af[mf][3] = __float_as_uint(As[rb + g + 8][k + t + 4]);
            }
            #pragma unroll
            for (int nf = 0; nf < 8; ++nf) {
                int cb = wn * 64 + nf * 8 + g;
                bf[nf][0] = __float_as_uint(Bs[k + t][cb]);
                bf[nf][1] = __float_as_uint(Bs[k + t + 4][cb]);
            }
            #pragma unroll
            for (int mf = 0; mf < 2; ++mf)
                #pragma unroll
                for (int nf = 0; nf < 8; ++nf)
                    mma_tf32(acc[mf][nf], af[mf], bf[nf]);
        }
        __syncthreads();
    }

    #pragma unroll
    for (int mf = 0; mf < 2; ++mf) {
        #pragma unroll
        for (int nf = 0; nf < 8; ++nf) {
            int col  = bcol + wn * 64 + nf * 8 + 2 * t;
            int row0 = brow + wm * 32 + mf * 16 + g;
            float2 bi = *reinterpret_cast<const float2*>(&bias[col]);
            float2 o0 = make_float2(acc[mf][nf][0] + bi.x, acc[mf][nf][1] + bi.y);
            float2 o1 = make_float2(acc[mf][nf][2] + bi.x, acc[mf][nf][3] + bi.y);
            *reinterpret_cast<float2*>(&C[(size_t)row0 * N + col]) = o0;
            *reinterpret_cast<float2*>(&C[(size_t)(row0 + 8) * N + col]) = o1;
        }
    }
}

// ---------------- tensor-core flash attention (causal + key-padding), tf32 mma ----------------
// Block = (64-row q-tile, head, batch), 256 threads = 8 warps.
// mma decomposition: warp (wm = warp>>1) owns 16 q-rows, (wn = warp&1) owns 32 cols.
// S = Q K^T and O += P V both via m16n8k8 tf32 mma; B-fragments read directly from
// natural [key][d] K/V smem tiles (row.col B layout == [n][k] row-major storage).
// Softmax is scalar: warp owns 8 rows, communicates alpha / 1/l via smem.
// Strides: PSTR=68 (A-frag bank = 4g+t, conflict-free), KSTR2=72 (B-frag bank = 8t+g, cf).

#define PSTR 68
#define KSTR2 72
#define SM_PS2  0                         // Q staging, then S/P tile: 64*68
#define SM_KS2  (64*PSTR)                 // K tile [key][d]: 64*68
#define SM_VS2  (SM_KS2 + 64*PSTR)       // V tile [key][d]: 64*72
#define SM_MA2  (SM_VS2 + 64*KSTR2)      // key mask add: 64
#define SM_AL2  (SM_MA2 + 64)            // per-row alpha: 64
#define SM_LI2  (SM_AL2 + 64)            // per-row 1/l: 64
#define ATT2_SMEM_FLOATS (SM_LI2 + 64)

__global__ __launch_bounds__(256, 2)
void attn_mma_kernel(const float* __restrict__ q, const float* __restrict__ kv,
                     const unsigned char* __restrict__ mask, float* __restrict__ o) {
    extern __shared__ float sm[];
    float* Ps  = sm + SM_PS2;
    float* Ks  = sm + SM_KS2;
    float* Vs  = sm + SM_VS2;
    float* Ma  = sm + SM_MA2;
    float* Sal = sm + SM_AL2;
    float* Sli = sm + SM_LI2;

    const int qt = blockIdx.x;
    const int h  = blockIdx.y;
    const int b  = blockIdx.z;
    const int tid  = threadIdx.x;
    const int warp = tid >> 5;
    const int lane = tid & 31;
    const int g = lane >> 2, t = lane & 3;
    const int wm = warp >> 1;            // 16-row slab 0..3
    const int wn = warp & 1;             // 32-col slab 0..1
    const int wrow = warp * 8;           // softmax row ownership
    const float scale = 0.125f;

    // ---- stage Q (pre-scaled, tf32) into Ps buffer, coalesced ----
    for (int idx = tid; idx < 64 * 64; idx += 256) {
        int r = idx >> 6, d = idx & 63;
        Ps[r * PSTR + d] = tf32r(q[(size_t)(b * LL + qt * 64 + r) * HD + h * DH + d] * scale);
    }
    __syncthreads();

    // ---- Q fragments resident in registers for the whole kt loop ----
    uint32_t qf[8][4];
    #pragma unroll
    for (int ks = 0; ks < 8; ++ks) {
        int rb = wm * 16, c = ks * 8;
        qf[ks][0] = __float_as_uint(Ps[(rb + g) * PSTR + c + t]);
        qf[ks][1] = __float_as_uint(Ps[(rb + g + 8) * PSTR + c + t]);
        qf[ks][2] = __float_as_uint(Ps[(rb + g) * PSTR + c + t + 4]);
        qf[ks][3] = __float_as_uint(Ps[(rb + g + 8) * PSTR + c + t + 4]);
    }
    __syncthreads();     // Ps buffer now free for S/P tiles

    float oacc[4][4];
    #pragma unroll
    for (int nf = 0; nf < 4; ++nf)
        #pragma unroll
        for (int r = 0; r < 4; ++r) oacc[nf][r] = 0.0f;
    float mrow[8], lrow[8];
    #pragma unroll
    for (int rr = 0; rr < 8; ++rr) { mrow[rr] = -CUDART_INF_F; lrow[rr] = 0.f; }

    for (int kt = 0; kt <= qt; ++kt) {
        // ---- stage K,V tiles [key][d] (tf32), coalesced + conflict-free ----
        for (int idx = tid; idx < 64 * 64; idx += 256) {
            int kk = idx >> 6, d = idx & 63;
            size_t base = (size_t)(b * LL + kt * 64 + kk) * (2 * HD) + h * DH + d;
            Ks[kk * PSTR  + d] = tf32r(kv[base]);
            Vs[kk * KSTR2 + d] = tf32r(kv[base + HD]);
        }
        if (tid < 64) Ma[tid] = mask[b * LL + kt * 64 + tid] ? -1e30f : 0.0f;
        __syncthreads();

        // ---- S = Q K^T via mma: warp computes 16x32 ----
        float sacc[4][4];
        #pragma unroll
        for (int nf = 0; nf < 4; ++nf)
            #pragma unroll
            for (int r = 0; r < 4; ++r) sacc[nf][r] = 0.0f;
        #pragma unroll
        for (int ks = 0; ks < 8; ++ks) {
            #pragma unroll
            for (int nf = 0; nf < 4; ++nf) {
                int key = wn * 32 + nf * 8 + g;
                uint32_t bf[2];
                bf[0] = __float_as_uint(Ks[key * PSTR + ks * 8 + t]);
                bf[1] = __float_as_uint(Ks[key * PSTR + ks * 8 + t + 4]);
                mma_tf32(sacc[nf], qf[ks], bf);
            }
        }
        // store S fragments to Ps
        #pragma unroll
        for (int nf = 0; nf < 4; ++nf) {
            int col = wn * 32 + nf * 8 + 2 * t;
            int row = wm * 16 + g;
            *reinterpret_cast<float2*>(&Ps[row * PSTR + col]) = make_float2(sacc[nf][0], sacc[nf][1]);
            *reinterpret_cast<float2*>(&Ps[(row + 8) * PSTR + col]) = make_float2(sacc[nf][2], sacc[nf][3]);
        }
        __syncthreads();

        // ---- scalar online softmax: warp owns rows wrow..wrow+7 ----
        const float ma0 = Ma[2 * lane], ma1 = Ma[2 * lane + 1];
        const bool diag = (kt == qt);
        #pragma unroll
        for (int rr = 0; rr < 8; ++rr) {
            int r = wrow + rr;
            float2 s2 = *reinterpret_cast<const float2*>(&Ps[r * PSTR + 2 * lane]);
            float s0 = s2.x + ma0;
            float s1 = s2.y + ma1;
            if (diag) {
                if (2 * lane > r)     s0 = -1e30f;
                if (2 * lane + 1 > r) s1 = -1e30f;
            }
            float mx = fmaxf(s0, s1);
            #pragma unroll
            for (int off = 16; off > 0; off >>= 1)
                mx = fmaxf(mx, __shfl_xor_sync(0xffffffffu, mx, off));
            float mnew = fmaxf(mrow[rr], mx);
            float p0 = __expf(s0 - mnew);
            float p1 = __expf(s1 - mnew);
            float ps = p0 + p1;
            #pragma unroll
            for (int off = 16; off > 0; off >>= 1)
                ps += __shfl_xor_sync(0xffffffffu, ps, off);
            float alpha = __expf(mrow[rr] - mnew);
            lrow[rr] = lrow[rr] * alpha + ps;
            mrow[rr] = mnew;
            *reinterpret_cast<float2*>(&Ps[r * PSTR + 2 * lane]) = make_float2(tf32r(p0), tf32r(p1));
            if (lane == 0) Sal[r] = alpha;
        }
        __syncthreads();

        // ---- O = O*alpha + P V via mma ----
        {
            float alo = Sal[wm * 16 + g];
            float ahi = Sal[wm * 16 + g + 8];
            #pragma unroll
            for (int nf = 0; nf < 4; ++nf) {
                oacc[nf][0] *= alo; oacc[nf][1] *= alo;
                oacc[nf][2] *= ahi; oacc[nf][3] *= ahi;
            }
        }
        #pragma unroll
        for (int ks = 0; ks < 8; ++ks) {
            uint32_t pa[4];
            int rb = wm * 16, c = ks * 8;
            pa[0] = __float_as_uint(Ps[(rb + g) * PSTR + c + t]);
            pa[1] = __float_as_uint(Ps[(rb + g + 8) * PSTR + c + t]);
            pa[2] = __float_as_uint(Ps[(rb + g) * PSTR + c + t + 4]);
            pa[3] = __float_as_uint(Ps[(rb + g + 8) * PSTR + c + t + 4]);
            #pragma unroll
            for (int nf = 0; nf < 4; ++nf) {
                int d = wn * 32 + nf * 8 + g;
                uint32_t bf[2];
                bf[0] = __float_as_uint(Vs[(c + t) * KSTR2 + d]);
                bf[1] = __float_as_uint(Vs[(c + t + 4) * KSTR2 + d]);
                mma_tf32(oacc[nf], pa, bf);
            }
        }
        __syncthreads();   // before tiles are overwritten
    }

    // ---- epilogue: 1/l via smem, normalize, store ----
    #pragma unroll
    for (int rr = 0; rr < 8; ++rr)
        if (lane == 0) Sli[wrow + rr] = 1.0f / lrow[rr];
    __syncthreads();

    {
        float llo = Sli[wm * 16 + g];
        float lhi = Sli[wm * 16 + g + 8];
        #pragma unroll
        for (int nf = 0; nf < 4; ++nf) {
            int col = h * DH + wn * 32 + nf * 8 + 2 * t;
            size_t row0 = (size_t)(b * LL + qt * 64 + wm * 16 + g);
            *reinterpret_cast<float2*>(&o[row0 * HD + col]) =
                make_float2(oacc[nf][0] * llo, oacc[nf][1] * llo);
            *reinterpret_cast<float2*>(&o[(row0 + 8) * HD + col]) =
                make_float2(oacc[nf][2] * lhi, oacc[nf][3] * lhi);
        }
    }
}

// ---------------- launch ----------------
extern "C" void kernel_launch(void* const* d_in, const int* in_sizes, int n_in,
                              void* d_out, int out_size) {
    const float*         x      = (const float*)d_in[0];
    const float*         y      = (const float*)d_in[1];
    const unsigned char* mask   = (const unsigned char*)d_in[2];
    const float*         Wq_w   = (const float*)d_in[3];
    const float*         Wq_b   = (const float*)d_in[4];
    const float*         Wkv_w  = (const float*)d_in[5];
    const float*         Wkv_b  = (const float*)d_in[6];
    const float*         proj_w = (const float*)d_in[7];
    const float*         proj_b = (const float*)d_in[8];
    float*               out    = (float*)d_out;

    void *pq = nullptr, *pkv = nullptr, *pattn = nullptr;
    cudaGetSymbolAddress(&pq, g_q);
    cudaGetSymbolAddress(&pkv, g_kv);
    cudaGetSymbolAddress(&pattn, g_attn);
    float* q_buf    = (float*)pq;
    float* kv_buf   = (float*)pkv;
    float* attn_buf = (float*)pattn;

    const int att_smem = ATT2_SMEM_FLOATS * sizeof(float);   // ~53 KB
    cudaFuncSetAttribute(attn_mma_kernel, cudaFuncAttributeMaxDynamicSharedMemorySize, att_smem);

    // q = x @ Wq + b            (4096 x 1024 x 1024)
    tf32gemm_bias<<<dim3(HD / GBN, ML / GBM), 256>>>(x, Wq_w, Wq_b, q_buf, ML, HD, HD);
    // kv = y @ Wkv + b          (4096 x 2048 x 1024)
    tf32gemm_bias<<<dim3(2 * HD / GBN, ML / GBM), 256>>>(y, Wkv_w, Wkv_b, kv_buf, ML, 2 * HD, HD);
    // attention (tensor-core)
    attn_mma_kernel<<<dim3(LL / 64, NH, BB), 256, att_smem>>>(q_buf, kv_buf, mask, attn_buf);
    // out = attn @ proj + b     (4096 x 1024 x 1024)
    tf32gemm_bias<<<dim3(HD / GBN, ML / GBM), 256>>>(attn_buf, proj_w, proj_b, out, ML, HD, HD);
}